// round 1
// baseline (speedup 1.0000x reference)
#include <cuda_runtime.h>

// MorphLayer == conv2d(x, exp(k1)-exp(k2), VALID 3x3) + bias   (exact algebraic reduction)
// B=32 C=64 H=W=64 -> Ho=Wo=62, F=128, K = 9*64 = 576.
//
// Implicit-GEMM fp32 conv using Blackwell packed fma.rn.f32x2 (FFMA2).
// Per block: M=128 spatial (8h x 16w), N=128 filters, K streamed in tiles of 16.
// x halo slab resident in SMEM (conflict-free padded stride 21),
// weights pre-exponentiated + duplicated (f32x2) once, B tiles via cp.async.

#define Bn  32
#define Cn  64
#define Hn  64
#define Wn  64
#define HOn 62
#define WOn 62
#define Fn  128
#define Kn  576
#define KTn 16
#define NTn 36            // 576/16

#define SLAB_H 10
#define SLAB_W 21         // 20 loaded + 1 pad word -> conflict-free scalar LDS
#define SLAB_FLOATS (Cn * SLAB_H * SLAB_W)                 // 13440
#define SMEM_BYTES  (SLAB_FLOATS * 4 + 2 * KTn * Fn * 8)   // 53760 + 32768 = 86528

// Pre-exponentiated, pair-duplicated weights: g_WdDup[k*128+f] = (w,w) packed, w = exp(k1)-exp(k2)
__device__ unsigned long long g_WdDup[Kn * Fn];

__device__ __forceinline__ unsigned long long pack2f(float lo, float hi) {
    unsigned long long r;
    asm("mov.b64 %0, {%1, %2};" : "=l"(r) : "f"(lo), "f"(hi));
    return r;
}
__device__ __forceinline__ void unpack2f(unsigned long long v, float& lo, float& hi) {
    asm("mov.b64 {%0, %1}, %2;" : "=f"(lo), "=f"(hi) : "l"(v));
}
__device__ __forceinline__ unsigned long long ffma2(unsigned long long a,
                                                    unsigned long long b,
                                                    unsigned long long c) {
    unsigned long long d;
    asm("fma.rn.f32x2 %0, %1, %2, %3;" : "=l"(d) : "l"(a), "l"(b), "l"(c));
    return d;
}

__global__ void prep_weights_kernel(const float* __restrict__ k1,
                                    const float* __restrict__ k2) {
    int i = blockIdx.x * 256 + threadIdx.x;   // grid sized exactly: 288*256 = 73728
    float w = expf(k1[i]) - expf(k2[i]);
    g_WdDup[i] = pack2f(w, w);
}

__device__ __forceinline__ void prefetch_b(const unsigned long long* __restrict__ src,
                                           unsigned long long* dst, int tid) {
    #pragma unroll
    for (int j = 0; j < 4; j++) {
        int off = (tid + j * 256) * 2;          // 1024 x 16B chunks cover 2048 ull
        unsigned da = (unsigned)__cvta_generic_to_shared(dst + off);
        asm volatile("cp.async.cg.shared.global [%0], [%1], 16;"
                     :: "r"(da), "l"(src + off));
    }
    asm volatile("cp.async.commit_group;");
}

extern __shared__ char smem_raw[];

__global__ void __launch_bounds__(256, 2)
conv_main_kernel(const float* __restrict__ x,
                 const float* __restrict__ bias,
                 float* __restrict__ out) {
    float* slab = (float*)smem_raw;                                   // [C][10][21]
    unsigned long long* Bsm = (unsigned long long*)(smem_raw + SLAB_FLOATS * 4); // [2][16][128]

    const int tid = threadIdx.x;
    const int tx = tid & 15;
    const int ty = tid >> 4;
    const int bz = blockIdx.z;          // batch
    const int h0 = blockIdx.y * 8;      // 8 h-tiles
    const int w0 = blockIdx.x * 16;     // 4 w-tiles

    // ---- Load x halo slab: x[bz, 0..63, h0..h0+9, w0..w0+19], zero-filled OOB ----
    const float* xb = x + (size_t)bz * Cn * Hn * Wn;
    for (int t = tid; t < Cn * SLAB_H * 5; t += 256) {   // 3200 float4 chunks
        int q  = t % 5;
        int r  = t / 5;
        int hh = r % SLAB_H;
        int c  = r / SLAB_H;
        int gh = h0 + hh;
        int gw = w0 + q * 4;
        float4 v = make_float4(0.f, 0.f, 0.f, 0.f);
        if (gh < Hn && gw + 3 < Wn)    // gw only ever fully-in or fully-out (w0%16==0)
            v = *(const float4*)(xb + ((c * Hn + gh) * Wn + gw));
        float* drow = slab + (c * SLAB_H + hh) * SLAB_W + q * 4;
        drow[0] = v.x; drow[1] = v.y; drow[2] = v.z; drow[3] = v.w;
    }

    prefetch_b(g_WdDup, Bsm, tid);      // tile 0 -> buf 0

    unsigned long long acc[8][4];
    #pragma unroll
    for (int i = 0; i < 8; i++)
        #pragma unroll
        for (int q = 0; q < 4; q++) acc[i][q] = 0ull;

    const int rowg0 = tx >> 2;          // thread's row within group (g adds +4)
    const int colb  = (tx & 3) * 4;     // thread's col base within 16-wide tile

    for (int kt = 0; kt < NTn; kt++) {
        int ktn = (kt + 1 < NTn) ? (kt + 1) : 0;   // dummy wrap on last iter (harmless)
        prefetch_b(g_WdDup + (size_t)ktn * KTn * Fn, Bsm + ((kt + 1) & 1) * KTn * Fn, tid);
        asm volatile("cp.async.wait_group 1;");
        __syncthreads();                 // tile kt resident for everyone

        const int kidx = kt >> 2;        // k = kidx*64 + c ; kidx fixed per 4 tiles
        const int c0   = (kt & 3) * 16;
        const int ki   = kidx / 3;
        const int kj   = kidx % 3;

        const unsigned long long* Bcur = Bsm + (kt & 1) * KTn * Fn + ty * 8;
        const float* a0base = slab + ((rowg0 + ki) * SLAB_W + colb + kj);
        const float* a1base = a0base + 4 * SLAB_W;

        #pragma unroll
        for (int kk = 0; kk < KTn; kk++) {
            const int c = c0 + kk;
            const float* ap0 = a0base + c * (SLAB_H * SLAB_W);
            const float* ap1 = a1base + c * (SLAB_H * SLAB_W);
            float a00 = ap0[0], a01 = ap0[1], a02 = ap0[2], a03 = ap0[3];
            float a10 = ap1[0], a11 = ap1[1], a12 = ap1[2], a13 = ap1[3];
            unsigned long long p0 = pack2f(a00, a01);
            unsigned long long p1 = pack2f(a02, a03);
            unsigned long long p2 = pack2f(a10, a11);
            unsigned long long p3 = pack2f(a12, a13);
            const unsigned long long* brow = Bcur + kk * Fn;
            #pragma unroll
            for (int ff = 0; ff < 8; ff++) {
                unsigned long long bd = brow[ff];
                acc[ff][0] = ffma2(p0, bd, acc[ff][0]);
                acc[ff][1] = ffma2(p1, bd, acc[ff][1]);
                acc[ff][2] = ffma2(p2, bd, acc[ff][2]);
                acc[ff][3] = ffma2(p3, bd, acc[ff][3]);
            }
        }
        __syncthreads();                 // done reading buf kt before it is refilled
    }

    // ---- Epilogue: y[bz, f, oh, ow] = acc + bias[f] ----
    #pragma unroll
    for (int ff = 0; ff < 8; ff++) {
        const int f = ty * 8 + ff;
        const float bv = __ldg(bias + f);
        #pragma unroll
        for (int g = 0; g < 2; g++) {
            const int oh = h0 + g * 4 + rowg0;
            if (oh >= HOn) continue;
            const int owb = w0 + colb;
            float v0, v1, v2, v3;
            unpack2f(acc[ff][g * 2 + 0], v0, v1);
            unpack2f(acc[ff][g * 2 + 1], v2, v3);
            float* orow = out + (((size_t)bz * Fn + f) * HOn + oh) * WOn + owb;
            if (owb + 0 < WOn) orow[0] = v0 + bv;
            if (owb + 1 < WOn) orow[1] = v1 + bv;
            if (owb + 2 < WOn) orow[2] = v2 + bv;
            if (owb + 3 < WOn) orow[3] = v3 + bv;
        }
    }
}

extern "C" void kernel_launch(void* const* d_in, const int* in_sizes, int n_in,
                              void* d_out, int out_size) {
    const float* x    = (const float*)d_in[0];   // (32,64,64,64)
    const float* k1   = (const float*)d_in[1];   // (3,3,64,128)
    const float* k2   = (const float*)d_in[2];   // (3,3,64,128)
    const float* bias = (const float*)d_in[3];   // (128,)
    float* out = (float*)d_out;                  // (32,128,62,62)

    (void)in_sizes; (void)n_in; (void)out_size;

    cudaFuncSetAttribute(conv_main_kernel,
                         cudaFuncAttributeMaxDynamicSharedMemorySize, SMEM_BYTES);

    prep_weights_kernel<<<(Kn * Fn) / 256, 256>>>(k1, k2);

    dim3 grid(4, 8, Bn);   // (w-tiles, h-tiles, batch) = 1024 blocks
    conv_main_kernel<<<grid, 256, SMEM_BYTES>>>(x, bias, out);
}

// round 3
// speedup vs baseline: 2.5523x; 2.5523x over previous
#include <cuda_runtime.h>
#include <cuda_bf16.h>
#include <cstdint>

// MorphLayer == conv2d(x, exp(k1)-exp(k2), VALID 3x3) + bias  (exact reduction)
// B=32 C=64 H=W=64 -> Ho=Wo=62, F=128.
// Warp-level HMMA (mma.sync m16n8k16 bf16) implicit-GEMM. Slab stored as
// [h*64+w][c] bf16 rows (128B) so each 3x3 tap is a pure row offset.
// 3-way bf16 split (x_hi*w_hi + x_lo*w_hi + x_hi*w_lo), fp32 accumulators.
// NOTE: harness ptxas targets bare sm_103 -> tcgen05 unavailable; mma.sync is.

#define Hn  64
#define Wn  64
#define HOn 62
#define WOn 62
#define Fn  128
#define Cn  64

#define SLAB_ROWS 388                      // 6*64 real + 4 pad (kj wrap)
#define SLAB_BYTES (SLAB_ROWS * 128)       // 49664
#define SLAB_HI 0
#define SLAB_LO SLAB_BYTES
#define WBUF    (2 * SLAB_BYTES)           // 99328; 2 bufs x (16KB hi + 16KB lo)
#define SMEM_TOTAL (WBUF + 2 * 32768)      // 164864

// Pre-split weights, SW128-swizzled, layout [tap][f=128][c=64] bf16 (128B rows)
__device__ __align__(16) unsigned char g_Whi[9 * 16384];
__device__ __align__(16) unsigned char g_Wlo[9 * 16384];

__device__ __forceinline__ uint32_t smem_u32(const void* p) {
    uint32_t a;
    asm("{ .reg .u64 t; cvta.to.shared.u64 t, %1; cvt.u32.u64 %0, t; }" : "=r"(a) : "l"(p));
    return a;
}

#define LDSM4(r, addr)                                                          \
    asm volatile("ldmatrix.sync.aligned.m8n8.x4.shared.b16 {%0,%1,%2,%3}, [%4];" \
                 : "=r"((r)[0]), "=r"((r)[1]), "=r"((r)[2]), "=r"((r)[3])        \
                 : "r"(addr))

#define MMA(d, a, b0, b1)                                                       \
    asm volatile("mma.sync.aligned.m16n8k16.row.col.f32.bf16.bf16.f32 "         \
                 "{%0,%1,%2,%3}, {%4,%5,%6,%7}, {%8,%9}, {%0,%1,%2,%3};"        \
                 : "+f"((d)[0]), "+f"((d)[1]), "+f"((d)[2]), "+f"((d)[3])        \
                 : "r"((a)[0]), "r"((a)[1]), "r"((a)[2]), "r"((a)[3]),           \
                   "r"(b0), "r"(b1))

// ---------------- weight prep: w = exp(k1)-exp(k2), bf16 hi/lo split ----------------
__global__ void prep_w(const float* __restrict__ k1, const float* __restrict__ k2) {
    int idx = blockIdx.x * 256 + threadIdx.x;       // 73728 = 9*128*64
    int t   = idx >> 13;                            // tap = ki*3+kj
    int rem = idx & 8191;
    int f   = rem >> 6;
    int c   = rem & 63;
    int src = (t * 64 + c) * 128 + f;               // k1 layout (kh,kw,C,F)
    float w = expf(k1[src]) - expf(k2[src]);
    __nv_bfloat16 hi = __float2bfloat16(w);
    float wl = w - __bfloat162float(hi);
    __nv_bfloat16 lo = __float2bfloat16(wl);
    unsigned off = (unsigned)(f * 128 + c * 2);
    off = off ^ ((off >> 3) & 0x70);                // SW128 swizzle
    *(unsigned short*)(g_Whi + t * 16384 + off) = *(unsigned short*)&hi;
    *(unsigned short*)(g_Wlo + t * 16384 + off) = *(unsigned short*)&lo;
}

// ---------------- main kernel ----------------
extern __shared__ char smem_raw[];

__global__ void __launch_bounds__(256, 1)
conv_hmma_kernel(const float* __restrict__ x,
                 const float* __restrict__ bias,
                 float* __restrict__ out) {
    const int tid  = threadIdx.x;
    const int lane = tid & 31;
    const int wid  = tid >> 5;
    const int wm   = wid & 3;          // warp M block (one output row, 64 w)
    const int wn   = wid >> 2;         // warp N block (64 filters)
    const int h0   = blockIdx.x * 4;   // 4 output rows per CTA
    const int bz   = blockIdx.y;

    const uint32_t sb = smem_u32(smem_raw);

    // ---- prefetch tap 0 weights (overlap with slab build) ----
    {
        uint32_t dst = sb + WBUF;
        const unsigned char* sh = g_Whi;
        const unsigned char* sl = g_Wlo;
        #pragma unroll
        for (int j = 0; j < 4; j++) {
            int off = (tid + j * 256) * 16;
            asm volatile("cp.async.cg.shared.global [%0], [%1], 16;"
                         :: "r"(dst + off), "l"(sh + off));
            asm volatile("cp.async.cg.shared.global [%0], [%1], 16;"
                         :: "r"(dst + 16384 + off), "l"(sl + off));
        }
        asm volatile("cp.async.commit_group;");
    }

    // ---- zero pad rows 384..387 of both slabs ----
    if (tid < 64) {
        uint32_t off = 384 * 128 + (tid & 31) * 16;
        char* base = smem_raw + ((tid < 32) ? SLAB_HI : SLAB_LO);
        *(uint4*)(base + off) = make_uint4(0u, 0u, 0u, 0u);
    }

    // ---- slab: x[bz, :, h0..h0+5, :] -> bf16 hi/lo, row=(hloc*64+w), 64 c ----
    const float* xb = x + (size_t)bz * Cn * Hn * Wn;
    #pragma unroll 1
    for (int it = 0; it < 12; it++) {
        int t    = tid + it * 256;     // 3072 tasks
        int gw   = t & 63;
        int cg   = (t >> 6) & 7;       // 8 channels per task
        int hloc = t >> 9;             // 0..5
        int gh   = h0 + hloc;
        float v[8];
        if (gh < Hn) {
            const float* xp = xb + (size_t)(cg * 8) * (Hn * Wn) + gh * Wn + gw;
            #pragma unroll
            for (int i = 0; i < 8; i++) v[i] = xp[(size_t)i * (Hn * Wn)];
        } else {
            #pragma unroll
            for (int i = 0; i < 8; i++) v[i] = 0.0f;
        }
        unsigned short hs[8], ls[8];
        #pragma unroll
        for (int i = 0; i < 8; i++) {
            __nv_bfloat16 h = __float2bfloat16(v[i]);
            hs[i] = *(unsigned short*)&h;
            float r = v[i] - __bfloat162float(h);
            __nv_bfloat16 l = __float2bfloat16(r);
            ls[i] = *(unsigned short*)&l;
        }
        unsigned row  = (unsigned)(hloc * 64 + gw);
        unsigned boff = row * 128 + cg * 16;
        unsigned sw   = boff ^ ((boff >> 3) & 0x70);
        uint4 ph = make_uint4((uint32_t)hs[0] | ((uint32_t)hs[1] << 16),
                              (uint32_t)hs[2] | ((uint32_t)hs[3] << 16),
                              (uint32_t)hs[4] | ((uint32_t)hs[5] << 16),
                              (uint32_t)hs[6] | ((uint32_t)hs[7] << 16));
        uint4 pl = make_uint4((uint32_t)ls[0] | ((uint32_t)ls[1] << 16),
                              (uint32_t)ls[2] | ((uint32_t)ls[3] << 16),
                              (uint32_t)ls[4] | ((uint32_t)ls[5] << 16),
                              (uint32_t)ls[6] | ((uint32_t)ls[7] << 16));
        *(uint4*)(smem_raw + SLAB_HI + sw) = ph;
        *(uint4*)(smem_raw + SLAB_LO + sw) = pl;
    }

    // ---- accumulators ----
    float acc[4][8][4];
    #pragma unroll
    for (int mi = 0; mi < 4; mi++)
        #pragma unroll
        for (int ni = 0; ni < 8; ni++)
            #pragma unroll
            for (int q = 0; q < 4; q++) acc[mi][ni][q] = 0.0f;

    // lane-constant ldmatrix addressing pieces
    const int      a_lrow  = lane & 15;                          // m row within 16
    const uint32_t a_hi16  = (uint32_t)(lane >> 4) * 16;         // k half for A
    const int      fb0     = wn * 64 + (lane & 7) + ((lane >> 4) & 1) * 8;
    const uint32_t b_off16 = (uint32_t)((lane >> 3) & 1) * 16;   // k half for B
    const uint32_t swzB    = (uint32_t)(fb0 & 7) << 4;

    for (int t = 0; t < 9; t++) {
        if (t < 8) {   // prefetch tap t+1 into buffer (t+1)&1
            uint32_t dst = sb + WBUF + ((t + 1) & 1) * 32768;
            const unsigned char* sh = g_Whi + (t + 1) * 16384;
            const unsigned char* sl = g_Wlo + (t + 1) * 16384;
            #pragma unroll
            for (int j = 0; j < 4; j++) {
                int off = (tid + j * 256) * 16;
                asm volatile("cp.async.cg.shared.global [%0], [%1], 16;"
                             :: "r"(dst + off), "l"(sh + off));
                asm volatile("cp.async.cg.shared.global [%0], [%1], 16;"
                             :: "r"(dst + 16384 + off), "l"(sl + off));
            }
            asm volatile("cp.async.commit_group;");
            asm volatile("cp.async.wait_group 1;");
        } else {
            asm volatile("cp.async.wait_group 0;");
        }
        __syncthreads();   // tap t weights + slab (t==0) visible to all

        const int ki = t / 3, kj = t % 3;
        const int sbase = (wm + ki) * 64 + a_lrow + kj;          // spatial slab row
        const uint32_t swzA    = (uint32_t)(sbase & 7) << 4;
        const uint32_t aBaseHi = sb + SLAB_HI + (uint32_t)sbase * 128;
        const uint32_t aBaseLo = sb + SLAB_LO + (uint32_t)sbase * 128;
        const uint32_t wb      = sb + WBUF + (t & 1) * 32768;
        const uint32_t bBaseHi = wb + (uint32_t)fb0 * 128;
        const uint32_t bBaseLo = bBaseHi + 16384;

        #pragma unroll
        for (int kc = 0; kc < 4; kc++) {
            const uint32_t aoff = ((uint32_t)(kc * 32) + a_hi16) ^ swzA;
            const uint32_t boff = ((uint32_t)(kc * 32) + b_off16) ^ swzB;

            uint32_t Ah[4][4], Bf[4][4], Al[4][4];
            #pragma unroll
            for (int mi = 0; mi < 4; mi++) LDSM4(Ah[mi], aBaseHi + mi * 2048 + aoff);
            #pragma unroll
            for (int bi = 0; bi < 4; bi++) LDSM4(Bf[bi], bBaseHi + bi * 2048 + boff);
            #pragma unroll
            for (int mi = 0; mi < 4; mi++)
                #pragma unroll
                for (int g = 0; g < 4; g++) {
                    MMA(acc[mi][2 * g],     Ah[mi], Bf[g][0], Bf[g][1]);
                    MMA(acc[mi][2 * g + 1], Ah[mi], Bf[g][2], Bf[g][3]);
                }

            #pragma unroll
            for (int mi = 0; mi < 4; mi++) LDSM4(Al[mi], aBaseLo + mi * 2048 + aoff);
            #pragma unroll
            for (int mi = 0; mi < 4; mi++)
                #pragma unroll
                for (int g = 0; g < 4; g++) {
                    MMA(acc[mi][2 * g],     Al[mi], Bf[g][0], Bf[g][1]);
                    MMA(acc[mi][2 * g + 1], Al[mi], Bf[g][2], Bf[g][3]);
                }

            #pragma unroll
            for (int bi = 0; bi < 4; bi++) LDSM4(Bf[bi], bBaseLo + bi * 2048 + boff);
            #pragma unroll
            for (int mi = 0; mi < 4; mi++)
                #pragma unroll
                for (int g = 0; g < 4; g++) {
                    MMA(acc[mi][2 * g],     Ah[mi], Bf[g][0], Bf[g][1]);
                    MMA(acc[mi][2 * g + 1], Ah[mi], Bf[g][2], Bf[g][3]);
                }
        }
        __syncthreads();   // done reading buf (t&1) before it is refilled
    }

    // ---- epilogue: acc -> out[bz, f, oh, ow] + bias ----
    const int oh = h0 + wm;
    if (oh < HOn) {
        #pragma unroll
        for (int mi = 0; mi < 4; mi++) {
            const int w0 = mi * 16 + (lane >> 2);
            const int w1 = w0 + 8;
            #pragma unroll
            for (int ni = 0; ni < 8; ni++) {
                const int f = wn * 64 + ni * 8 + (lane & 3) * 2;
                const float b0 = __ldg(bias + f);
                const float b1 = __ldg(bias + f + 1);
                float* p0 = out + (((size_t)bz * Fn + f) * HOn + oh) * WOn;
                float* p1 = p0 + (size_t)HOn * WOn;
                if (w0 < WOn) {
                    p0[w0] = acc[mi][ni][0] + b0;
                    p1[w0] = acc[mi][ni][1] + b1;
                }
                if (w1 < WOn) {
                    p0[w1] = acc[mi][ni][2] + b0;
                    p1[w1] = acc[mi][ni][3] + b1;
                }
            }
        }
    }
}

extern "C" void kernel_launch(void* const* d_in, const int* in_sizes, int n_in,
                              void* d_out, int out_size) {
    const float* x    = (const float*)d_in[0];   // (32,64,64,64)
    const float* k1   = (const float*)d_in[1];   // (3,3,64,128)
    const float* k2   = (const float*)d_in[2];   // (3,3,64,128)
    const float* bias = (const float*)d_in[3];   // (128,)
    float* out = (float*)d_out;                  // (32,128,62,62)
    (void)in_sizes; (void)n_in; (void)out_size;

    cudaFuncSetAttribute(conv_hmma_kernel,
                         cudaFuncAttributeMaxDynamicSharedMemorySize, SMEM_TOTAL);

    prep_w<<<288, 256>>>(k1, k2);
    dim3 grid(16, 32);                 // 16 h-tiles x 32 batch = 512 CTAs
    conv_hmma_kernel<<<grid, 256, SMEM_TOTAL>>>(x, bias, out);
}

// round 4
// speedup vs baseline: 2.7183x; 1.0650x over previous
#include <cuda_runtime.h>
#include <cuda_bf16.h>
#include <cstdint>

// MorphLayer == conv2d(x, exp(k1)-exp(k2), VALID 3x3) + bias  (exact reduction)
// B=32 C=64 H=W=64 -> Ho=Wo=62, F=128.
// Warp-level HMMA implicit-GEMM, 3-way bf16 split, now sized for 2 CTAs/SM:
// CTA tile M=128 (2 rows x 64 w) x N=128, warp tile 64x32 (acc=64 regs),
// slab = 4 input rows (exact, no h waste; 31 h-tiles * 2 = 62 = Ho),
// weights double-buffered at 16KB (hi/lo chunk) granularity.

#define Hn  64
#define Wn  64
#define HOn 62
#define WOn 62
#define Fn  128
#define Cn  64

#define SLAB_ROWS  258                     // 4*64 real + 2 pad (kj wrap, mi*16 reach)
#define SLAB_BYTES (SLAB_ROWS * 128)       // 33024
#define SLAB_HI 0
#define SLAB_LO SLAB_BYTES
#define WBUF    (2 * SLAB_BYTES)           // 66048; 2 slots x 16KB
#define SMEM_TOTAL (WBUF + 2 * 16384)      // 98816  -> 2 CTAs/SM

// Pre-split weights, SW128-swizzled, layout [tap][f=128][c=64] bf16 (128B rows)
__device__ __align__(16) unsigned char g_Whi[9 * 16384];
__device__ __align__(16) unsigned char g_Wlo[9 * 16384];

__device__ __forceinline__ uint32_t smem_u32(const void* p) {
    uint32_t a;
    asm("{ .reg .u64 t; cvta.to.shared.u64 t, %1; cvt.u32.u64 %0, t; }" : "=r"(a) : "l"(p));
    return a;
}

#define LDSM4(r, addr)                                                          \
    asm volatile("ldmatrix.sync.aligned.m8n8.x4.shared.b16 {%0,%1,%2,%3}, [%4];" \
                 : "=r"((r)[0]), "=r"((r)[1]), "=r"((r)[2]), "=r"((r)[3])        \
                 : "r"(addr))

#define MMA(d, a, b0, b1)                                                       \
    asm volatile("mma.sync.aligned.m16n8k16.row.col.f32.bf16.bf16.f32 "         \
                 "{%0,%1,%2,%3}, {%4,%5,%6,%7}, {%8,%9}, {%0,%1,%2,%3};"        \
                 : "+f"((d)[0]), "+f"((d)[1]), "+f"((d)[2]), "+f"((d)[3])        \
                 : "r"((a)[0]), "r"((a)[1]), "r"((a)[2]), "r"((a)[3]),           \
                   "r"(b0), "r"(b1))

// ---------------- weight prep: w = exp(k1)-exp(k2), bf16 hi/lo split ----------------
__global__ void prep_w(const float* __restrict__ k1, const float* __restrict__ k2) {
    int idx = blockIdx.x * 256 + threadIdx.x;       // 73728 = 9*128*64
    int t   = idx >> 13;
    int rem = idx & 8191;
    int f   = rem >> 6;
    int c   = rem & 63;
    int src = (t * 64 + c) * 128 + f;               // k1 layout (kh,kw,C,F)
    float w = expf(k1[src]) - expf(k2[src]);
    __nv_bfloat16 hi = __float2bfloat16(w);
    float wl = w - __bfloat162float(hi);
    __nv_bfloat16 lo = __float2bfloat16(wl);
    unsigned off = (unsigned)(f * 128 + c * 2);
    off = off ^ ((off >> 3) & 0x70);                // SW128 swizzle
    *(unsigned short*)(g_Whi + t * 16384 + off) = *(unsigned short*)&hi;
    *(unsigned short*)(g_Wlo + t * 16384 + off) = *(unsigned short*)&lo;
}

// ---------------- main kernel ----------------
extern __shared__ char smem_raw[];

__device__ __forceinline__ void load_chunk(uint32_t dst, const unsigned char* src,
                                           int tid) {
    #pragma unroll
    for (int j = 0; j < 4; j++) {
        uint32_t off = (uint32_t)tid * 64 + j * 16;
        asm volatile("cp.async.cg.shared.global [%0], [%1], 16;"
                     :: "r"(dst + off), "l"(src + off));
    }
    asm volatile("cp.async.commit_group;");
}

template <bool TWO_A>
__device__ __forceinline__ void do_phase(float acc[4][4][4],
                                         uint32_t aBase1, uint32_t aBase2,
                                         uint32_t bBase,
                                         uint32_t swzA, uint32_t a_hi16,
                                         uint32_t b_off16, uint32_t swzB) {
    #pragma unroll
    for (int kc = 0; kc < 4; kc++) {
        const uint32_t aoff = ((uint32_t)(kc * 32) + a_hi16) ^ swzA;
        const uint32_t boff = ((uint32_t)(kc * 32) + b_off16) ^ swzB;
        uint32_t Bf[2][4], A[4][4];
        LDSM4(Bf[0], bBase + boff);
        LDSM4(Bf[1], bBase + 2048 + boff);
        #pragma unroll
        for (int mi = 0; mi < 4; mi++) LDSM4(A[mi], aBase1 + mi * 2048 + aoff);
        #pragma unroll
        for (int mi = 0; mi < 4; mi++)
            #pragma unroll
            for (int bi = 0; bi < 2; bi++) {
                MMA(acc[mi][2 * bi],     A[mi], Bf[bi][0], Bf[bi][1]);
                MMA(acc[mi][2 * bi + 1], A[mi], Bf[bi][2], Bf[bi][3]);
            }
        if (TWO_A) {
            #pragma unroll
            for (int mi = 0; mi < 4; mi++) LDSM4(A[mi], aBase2 + mi * 2048 + aoff);
            #pragma unroll
            for (int mi = 0; mi < 4; mi++)
                #pragma unroll
                for (int bi = 0; bi < 2; bi++) {
                    MMA(acc[mi][2 * bi],     A[mi], Bf[bi][0], Bf[bi][1]);
                    MMA(acc[mi][2 * bi + 1], A[mi], Bf[bi][2], Bf[bi][3]);
                }
        }
    }
}

__global__ void __launch_bounds__(256, 2)
conv_hmma_kernel(const float* __restrict__ x,
                 const float* __restrict__ bias,
                 float* __restrict__ out) {
    const int tid  = threadIdx.x;
    const int lane = tid & 31;
    const int wid  = tid >> 5;
    const int wm   = wid & 1;          // warp M block (one output row, 64 w)
    const int wn   = wid >> 1;         // warp N block (32 filters)
    const int h0   = blockIdx.x * 2;   // 2 output rows per CTA (31 tiles = 62 exact)
    const int bz   = blockIdx.y;

    const uint32_t sb = smem_u32(smem_raw);

    // preload chunk hi_0 -> slot 0 (overlaps slab build)
    load_chunk(sb + WBUF, g_Whi, tid);

    // zero pad rows 256..257 of both slabs
    if (tid < 32) {
        uint32_t off = 256 * 128 + (tid & 15) * 16;
        char* base = smem_raw + ((tid < 16) ? SLAB_HI : SLAB_LO);
        *(uint4*)(base + off) = make_uint4(0u, 0u, 0u, 0u);
    }

    // ---- slab: x[bz, :, h0..h0+3, :] -> bf16 hi/lo, row=(hloc*64+w), 64 c ----
    // h0 <= 60 so all 4 input rows are in bounds: no checks.
    const float* xb = x + (size_t)bz * Cn * Hn * Wn;
    #pragma unroll 1
    for (int it = 0; it < 8; it++) {
        int t    = tid + it * 256;     // 2048 tasks
        int gw   = t & 63;
        int cg   = (t >> 6) & 7;
        int hloc = t >> 9;             // 0..3
        const float* xp = xb + (size_t)(cg * 8) * (Hn * Wn) + (h0 + hloc) * Wn + gw;
        float v[8];
        #pragma unroll
        for (int i = 0; i < 8; i++) v[i] = xp[(size_t)i * (Hn * Wn)];
        unsigned short hs[8], ls[8];
        #pragma unroll
        for (int i = 0; i < 8; i++) {
            __nv_bfloat16 h = __float2bfloat16(v[i]);
            hs[i] = *(unsigned short*)&h;
            float r = v[i] - __bfloat162float(h);
            __nv_bfloat16 l = __float2bfloat16(r);
            ls[i] = *(unsigned short*)&l;
        }
        unsigned row  = (unsigned)(hloc * 64 + gw);
        unsigned boff = row * 128 + cg * 16;
        unsigned sw   = boff ^ ((boff >> 3) & 0x70);
        *(uint4*)(smem_raw + SLAB_HI + sw) =
            make_uint4((uint32_t)hs[0] | ((uint32_t)hs[1] << 16),
                       (uint32_t)hs[2] | ((uint32_t)hs[3] << 16),
                       (uint32_t)hs[4] | ((uint32_t)hs[5] << 16),
                       (uint32_t)hs[6] | ((uint32_t)hs[7] << 16));
        *(uint4*)(smem_raw + SLAB_LO + sw) =
            make_uint4((uint32_t)ls[0] | ((uint32_t)ls[1] << 16),
                       (uint32_t)ls[2] | ((uint32_t)ls[3] << 16),
                       (uint32_t)ls[4] | ((uint32_t)ls[5] << 16),
                       (uint32_t)ls[6] | ((uint32_t)ls[7] << 16));
    }

    float acc[4][4][4];
    #pragma unroll
    for (int mi = 0; mi < 4; mi++)
        #pragma unroll
        for (int ni = 0; ni < 4; ni++)
            #pragma unroll
            for (int q = 0; q < 4; q++) acc[mi][ni][q] = 0.0f;

    // lane-constant addressing
    const int      a_lrow  = lane & 15;
    const uint32_t a_hi16  = (uint32_t)(lane >> 4) * 16;
    const int      fb0     = wn * 32 + (lane & 7) + ((lane >> 4) & 1) * 8;
    const uint32_t b_off16 = (uint32_t)((lane >> 3) & 1) * 16;
    const uint32_t swzB    = (uint32_t)(fb0 & 7) << 4;
    const uint32_t slot0   = sb + WBUF;
    const uint32_t slot1   = sb + WBUF + 16384;

    #pragma unroll 1
    for (int t = 0; t < 9; t++) {
        const int ki = t / 3;
        const int kj = t - 3 * ki;
        const int sbase = (wm + ki) * 64 + a_lrow + kj;
        const uint32_t swzA = (uint32_t)(sbase & 7) << 4;
        const uint32_t aHi  = sb + SLAB_HI + (uint32_t)sbase * 128;
        const uint32_t aLo  = sb + SLAB_LO + (uint32_t)sbase * 128;
        const uint32_t bB   = (uint32_t)fb0 * 128;

        // prefetch lo_t -> slot1; hi_t (slot0) guaranteed done after wait 1
        load_chunk(slot1, g_Wlo + t * 16384, tid);
        asm volatile("cp.async.wait_group 1;");
        __syncthreads();
        // products 1 & 2: (A_hi + A_lo) x W_hi
        do_phase<true>(acc, aHi, aLo, slot0 + bB, swzA, a_hi16, b_off16, swzB);
        __syncthreads();

        // prefetch hi_{t+1} -> slot0; lo_t (slot1) guaranteed done
        if (t < 8) {
            load_chunk(slot0, g_Whi + (t + 1) * 16384, tid);
            asm volatile("cp.async.wait_group 1;");
        } else {
            asm volatile("cp.async.wait_group 0;");
        }
        __syncthreads();
        // product 3: A_hi x W_lo
        do_phase<false>(acc, aHi, 0u, slot1 + bB, swzA, a_hi16, b_off16, swzB);
        __syncthreads();
    }

    // ---- epilogue: acc -> out[bz, f, oh, ow] + bias (oh always valid) ----
    const int oh = h0 + wm;
    #pragma unroll
    for (int ni = 0; ni < 4; ni++) {
        const int f = wn * 32 + ni * 8 + (lane & 3) * 2;
        const float b0 = __ldg(bias + f);
        const float b1 = __ldg(bias + f + 1);
        float* p0 = out + (((size_t)bz * Fn + f) * HOn + oh) * WOn;
        float* p1 = p0 + (size_t)HOn * WOn;
        #pragma unroll
        for (int mi = 0; mi < 4; mi++) {
            const int w0 = mi * 16 + (lane >> 2);
            const int w1 = w0 + 8;
            if (w0 < WOn) {
                p0[w0] = acc[mi][ni][0] + b0;
                p1[w0] = acc[mi][ni][1] + b1;
            }
            if (w1 < WOn) {
                p0[w1] = acc[mi][ni][2] + b0;
                p1[w1] = acc[mi][ni][3] + b1;
            }
        }
    }
}

extern "C" void kernel_launch(void* const* d_in, const int* in_sizes, int n_in,
                              void* d_out, int out_size) {
    const float* x    = (const float*)d_in[0];   // (32,64,64,64)
    const float* k1   = (const float*)d_in[1];   // (3,3,64,128)
    const float* k2   = (const float*)d_in[2];   // (3,3,64,128)
    const float* bias = (const float*)d_in[3];   // (128,)
    float* out = (float*)d_out;                  // (32,128,62,62)
    (void)in_sizes; (void)n_in; (void)out_size;

    cudaFuncSetAttribute(conv_hmma_kernel,
                         cudaFuncAttributeMaxDynamicSharedMemorySize, SMEM_TOTAL);

    prep_w<<<288, 256>>>(k1, k2);
    dim3 grid(31, 32);                 // 31 h-tiles x 32 batch = 992 CTAs
    conv_hmma_kernel<<<grid, 256, SMEM_TOTAL>>>(x, bias, out);
}

// round 5
// speedup vs baseline: 2.7975x; 1.0291x over previous
#include <cuda_runtime.h>
#include <cuda_fp16.h>
#include <cstdint>

// MorphLayer == conv2d(x, exp(k1)-exp(k2), VALID 3x3) + bias  (exact reduction)
// B=32 C=64 H=W=64 -> Ho=Wo=62, F=128.
// Warp-level HMMA implicit-GEMM, fp16 2-product split:
//   y = x_f16 * (w_hi + w_lo),  w_hi/w_lo fp16, fp32 accumulation.
// Only uncompensated error is x->fp16 rounding (~1.4e-4 on output norm).
// CTA tile M=128 (2 output rows x 64 w) x N=128, warp tile 64x32.
// Slab: x fp16 [4*64+2 rows][64 c], SW128 swizzle; taps are row offsets.
// Weights streamed per tap (32KB hi+lo chunk), double buffered.

#define Hn  64
#define Wn  64
#define HOn 62
#define WOn 62
#define Fn  128
#define Cn  64

#define SLAB_ROWS  258                     // 4*64 real + 2 pad (kj wrap)
#define SLAB_BYTES (SLAB_ROWS * 128)       // 33024 (fp16, single copy)
#define WBUF       SLAB_BYTES              // 2 bufs x 32KB (hi 16K + lo 16K)
#define SMEM_TOTAL (WBUF + 2 * 32768)      // 98560 -> 2 CTAs/SM

// Pre-split weights, SW128-swizzled: [tap][part(hi/lo)][f=128][c=64] fp16
__device__ __align__(16) unsigned char g_W[9 * 32768];

__device__ __forceinline__ uint32_t smem_u32(const void* p) {
    uint32_t a;
    asm("{ .reg .u64 t; cvta.to.shared.u64 t, %1; cvt.u32.u64 %0, t; }" : "=r"(a) : "l"(p));
    return a;
}

#define LDSM4(r, addr)                                                          \
    asm volatile("ldmatrix.sync.aligned.m8n8.x4.shared.b16 {%0,%1,%2,%3}, [%4];" \
                 : "=r"((r)[0]), "=r"((r)[1]), "=r"((r)[2]), "=r"((r)[3])        \
                 : "r"(addr))

#define MMA(d, a, b0, b1)                                                       \
    asm volatile("mma.sync.aligned.m16n8k16.row.col.f32.f16.f16.f32 "           \
                 "{%0,%1,%2,%3}, {%4,%5,%6,%7}, {%8,%9}, {%0,%1,%2,%3};"        \
                 : "+f"((d)[0]), "+f"((d)[1]), "+f"((d)[2]), "+f"((d)[3])        \
                 : "r"((a)[0]), "r"((a)[1]), "r"((a)[2]), "r"((a)[3]),           \
                   "r"(b0), "r"(b1))

// ---------------- weight prep: w = exp(k1)-exp(k2), fp16 hi/lo split ----------------
__global__ void prep_w(const float* __restrict__ k1, const float* __restrict__ k2) {
    int idx = blockIdx.x * 256 + threadIdx.x;       // 73728 = 9*128*64
    int t   = idx >> 13;
    int rem = idx & 8191;
    int f   = rem >> 6;
    int c   = rem & 63;
    int src = (t * 64 + c) * 128 + f;               // k1 layout (kh,kw,C,F)
    float w = expf(k1[src]) - expf(k2[src]);
    __half hi = __float2half_rn(w);
    float wl = w - __half2float(hi);
    __half lo = __float2half_rn(wl);
    unsigned off = (unsigned)(f * 128 + c * 2);
    off = off ^ ((off >> 3) & 0x70);                // SW128 swizzle
    *(unsigned short*)(g_W + t * 32768 + off)         = *(unsigned short*)&hi;
    *(unsigned short*)(g_W + t * 32768 + 16384 + off) = *(unsigned short*)&lo;
}

// ---------------- main kernel ----------------
extern __shared__ char smem_raw[];

__device__ __forceinline__ void load_chunk32(uint32_t dst, const unsigned char* src,
                                             int tid) {
    #pragma unroll
    for (int j = 0; j < 8; j++) {
        uint32_t off = (uint32_t)tid * 128 + j * 16;
        asm volatile("cp.async.cg.shared.global [%0], [%1], 16;"
                     :: "r"(dst + off), "l"(src + off));
    }
    asm volatile("cp.async.commit_group;");
}

__global__ void __launch_bounds__(256, 2)
conv_hmma_kernel(const float* __restrict__ x,
                 const float* __restrict__ bias,
                 float* __restrict__ out) {
    const int tid  = threadIdx.x;
    const int lane = tid & 31;
    const int wid  = tid >> 5;
    const int wm   = wid & 1;          // warp M block (one output row, 64 w)
    const int wn   = wid >> 1;         // warp N block (32 filters)
    const int h0   = blockIdx.x * 2;   // 31 tiles * 2 = 62 = Ho exactly
    const int bz   = blockIdx.y;

    const uint32_t sb = smem_u32(smem_raw);

    // preload tap 0 chunk -> buf 0 (overlaps slab build)
    load_chunk32(sb + WBUF, g_W, tid);

    // zero pad rows 256..257 of slab
    if (tid < 16) {
        *(uint4*)(smem_raw + 256 * 128 + tid * 16) = make_uint4(0u, 0u, 0u, 0u);
    }

    // ---- slab: x[bz, :, h0..h0+3, :] -> fp16, row=(hloc*64+w), 64 c, SW128 ----
    const float* xb = x + (size_t)bz * Cn * Hn * Wn;
    #pragma unroll 1
    for (int it = 0; it < 8; it++) {
        int t    = tid + it * 256;     // 2048 tasks
        int gw   = t & 63;
        int cg   = (t >> 6) & 7;
        int hloc = t >> 9;             // 0..3 (all in bounds: h0 <= 60)
        const float* xp = xb + (size_t)(cg * 8) * (Hn * Wn) + (h0 + hloc) * Wn + gw;
        unsigned short hs[8];
        #pragma unroll
        for (int i = 0; i < 8; i++) {
            __half h = __float2half_rn(xp[(size_t)i * (Hn * Wn)]);
            hs[i] = *(unsigned short*)&h;
        }
        unsigned row  = (unsigned)(hloc * 64 + gw);
        unsigned boff = row * 128 + cg * 16;
        unsigned sw   = boff ^ ((boff >> 3) & 0x70);
        *(uint4*)(smem_raw + sw) =
            make_uint4((uint32_t)hs[0] | ((uint32_t)hs[1] << 16),
                       (uint32_t)hs[2] | ((uint32_t)hs[3] << 16),
                       (uint32_t)hs[4] | ((uint32_t)hs[5] << 16),
                       (uint32_t)hs[6] | ((uint32_t)hs[7] << 16));
    }

    float acc[4][4][4];
    #pragma unroll
    for (int mi = 0; mi < 4; mi++)
        #pragma unroll
        for (int ni = 0; ni < 4; ni++)
            #pragma unroll
            for (int q = 0; q < 4; q++) acc[mi][ni][q] = 0.0f;

    // lane-constant addressing
    const int      a_lrow  = lane & 15;
    const uint32_t a_hi16  = (uint32_t)(lane >> 4) * 16;
    const int      fb0     = wn * 32 + (lane & 7) + ((lane >> 4) & 1) * 8;
    const uint32_t b_off16 = (uint32_t)((lane >> 3) & 1) * 16;
    const uint32_t swzB    = (uint32_t)(fb0 & 7) << 4;

    #pragma unroll 1
    for (int t = 0; t < 9; t++) {
        if (t < 8) {
            load_chunk32(sb + WBUF + ((t + 1) & 1) * 32768,
                         g_W + (size_t)(t + 1) * 32768, tid);
            asm volatile("cp.async.wait_group 1;");
        } else {
            asm volatile("cp.async.wait_group 0;");
        }
        __syncthreads();   // tap t weights + slab (t==0) visible

        const int ki = t / 3;
        const int kj = t - 3 * ki;
        const int sbase = (wm + ki) * 64 + a_lrow + kj;
        const uint32_t swzA  = (uint32_t)(sbase & 7) << 4;
        const uint32_t aBase = sb + (uint32_t)sbase * 128;
        const uint32_t wbase = sb + WBUF + (t & 1) * 32768 + (uint32_t)fb0 * 128;

        #pragma unroll
        for (int kc = 0; kc < 4; kc++) {
            const uint32_t aoff = ((uint32_t)(kc * 32) + a_hi16) ^ swzA;
            const uint32_t boff = ((uint32_t)(kc * 32) + b_off16) ^ swzB;

            uint32_t A[4][4], Bh[2][4], Bl[2][4];
            #pragma unroll
            for (int mi = 0; mi < 4; mi++) LDSM4(A[mi], aBase + mi * 2048 + aoff);
            LDSM4(Bh[0], wbase + boff);
            LDSM4(Bh[1], wbase + 2048 + boff);
            LDSM4(Bl[0], wbase + 16384 + boff);
            LDSM4(Bl[1], wbase + 16384 + 2048 + boff);

            #pragma unroll
            for (int mi = 0; mi < 4; mi++)
                #pragma unroll
                for (int bi = 0; bi < 2; bi++) {
                    MMA(acc[mi][2 * bi],     A[mi], Bh[bi][0], Bh[bi][1]);
                    MMA(acc[mi][2 * bi + 1], A[mi], Bh[bi][2], Bh[bi][3]);
                }
            #pragma unroll
            for (int mi = 0; mi < 4; mi++)
                #pragma unroll
                for (int bi = 0; bi < 2; bi++) {
                    MMA(acc[mi][2 * bi],     A[mi], Bl[bi][0], Bl[bi][1]);
                    MMA(acc[mi][2 * bi + 1], A[mi], Bl[bi][2], Bl[bi][3]);
                }
        }
        __syncthreads();   // done reading buf (t&1) before it is refilled
    }

    // ---- epilogue: acc -> out[bz, f, oh, ow] + bias (oh always valid) ----
    const int oh = h0 + wm;
    #pragma unroll
    for (int ni = 0; ni < 4; ni++) {
        const int f = wn * 32 + ni * 8 + (lane & 3) * 2;
        const float b0 = __ldg(bias + f);
        const float b1 = __ldg(bias + f + 1);
        float* p0 = out + (((size_t)bz * Fn + f) * HOn + oh) * WOn;
        float* p1 = p0 + (size_t)HOn * WOn;
        #pragma unroll
        for (int mi = 0; mi < 4; mi++) {
            const int w0 = mi * 16 + (lane >> 2);
            const int w1 = w0 + 8;
            if (w0 < WOn) {
                p0[w0] = acc[mi][ni][0] + b0;
                p1[w0] = acc[mi][ni][1] + b1;
            }
            if (w1 < WOn) {
                p0[w1] = acc[mi][ni][2] + b0;
                p1[w1] = acc[mi][ni][3] + b1;
            }
        }
    }
}

extern "C" void kernel_launch(void* const* d_in, const int* in_sizes, int n_in,
                              void* d_out, int out_size) {
    const float* x    = (const float*)d_in[0];   // (32,64,64,64)
    const float* k1   = (const float*)d_in[1];   // (3,3,64,128)
    const float* k2   = (const float*)d_in[2];   // (3,3,64,128)
    const float* bias = (const float*)d_in[3];   // (128,)
    float* out = (float*)d_out;                  // (32,128,62,62)
    (void)in_sizes; (void)n_in; (void)out_size;

    cudaFuncSetAttribute(conv_hmma_kernel,
                         cudaFuncAttributeMaxDynamicSharedMemorySize, SMEM_TOTAL);

    prep_w<<<288, 256>>>(k1, k2);
    dim3 grid(31, 32);                 // 31 h-tiles x 32 batch = 992 CTAs
    conv_hmma_kernel<<<grid, 256, SMEM_TOTAL>>>(x, bias, out);
}

// round 6
// speedup vs baseline: 5.9121x; 2.1133x over previous
#include <cuda_runtime.h>
#include <cuda_fp16.h>
#include <cstdint>

// MorphLayer == conv2d(x, exp(k1)-exp(k2), VALID 3x3) + bias  (exact reduction)
// B=32 C=64 H=W=64 -> Ho=Wo=62, F=128.
// Warp-level HMMA implicit-GEMM, SINGLE fp16 product (x_f16 * w_f16, fp32 acc).
// Weights for this CTA's 64 filters are fully SMEM-resident (72KB) -> the
// mainloop has ZERO global loads and ZERO barriers. Slab: x fp16
// [4*64+2 rows][64 c] SW128; each 3x3 tap is a row offset.
// CTA tile M=128 (2 output rows x 64 w) x N=64; warp tile 32x32; 2 CTAs/SM.

#define Hn  64
#define Wn  64
#define HOn 62
#define WOn 62
#define Fn  128
#define Cn  64

#define SLAB_ROWS  258                     // 4*64 real + 2 pad (kj wrap)
#define SLAB_BYTES (SLAB_ROWS * 128)       // 33024
#define WOFF       SLAB_BYTES
#define WRES_BYTES (9 * 64 * 128)          // 73728 resident weights
#define SMEM_TOTAL (WOFF + WRES_BYTES)     // 106752 -> 2 CTAs/SM

// Single fp16 weights, SW128-swizzled: [tap][f=128][c=64]
__device__ __align__(16) unsigned char g_W[9 * 16384];

__device__ __forceinline__ uint32_t smem_u32(const void* p) {
    uint32_t a;
    asm("{ .reg .u64 t; cvta.to.shared.u64 t, %1; cvt.u32.u64 %0, t; }" : "=r"(a) : "l"(p));
    return a;
}

#define LDSM4(r, addr)                                                          \
    asm volatile("ldmatrix.sync.aligned.m8n8.x4.shared.b16 {%0,%1,%2,%3}, [%4];" \
                 : "=r"((r)[0]), "=r"((r)[1]), "=r"((r)[2]), "=r"((r)[3])        \
                 : "r"(addr))

#define MMA(d, a, b0, b1)                                                       \
    asm volatile("mma.sync.aligned.m16n8k16.row.col.f32.f16.f16.f32 "           \
                 "{%0,%1,%2,%3}, {%4,%5,%6,%7}, {%8,%9}, {%0,%1,%2,%3};"        \
                 : "+f"((d)[0]), "+f"((d)[1]), "+f"((d)[2]), "+f"((d)[3])        \
                 : "r"((a)[0]), "r"((a)[1]), "r"((a)[2]), "r"((a)[3]),           \
                   "r"(b0), "r"(b1))

// ---------------- weight prep: w = exp(k1)-exp(k2) -> fp16, swizzled ----------------
__global__ void prep_w(const float* __restrict__ k1, const float* __restrict__ k2) {
    int idx = blockIdx.x * 256 + threadIdx.x;       // 73728 = 9*128*64
    int t   = idx >> 13;
    int rem = idx & 8191;
    int f   = rem >> 6;
    int c   = rem & 63;
    int src = (t * 64 + c) * 128 + f;               // k1 layout (kh,kw,C,F)
    float w = expf(k1[src]) - expf(k2[src]);
    __half h = __float2half_rn(w);
    unsigned off = (unsigned)(f * 128 + c * 2);
    off = off ^ ((off >> 3) & 0x70);                // SW128 swizzle (within 128B row)
    *(unsigned short*)(g_W + t * 16384 + off) = *(unsigned short*)&h;
}

// ---------------- main kernel ----------------
extern __shared__ char smem_raw[];

__global__ void __launch_bounds__(256, 2)
conv_hmma_kernel(const float* __restrict__ x,
                 const float* __restrict__ bias,
                 float* __restrict__ out) {
    const int tid  = threadIdx.x;
    const int lane = tid & 31;
    const int wid  = tid >> 5;
    const int wm   = wid & 3;          // 4 M-blocks of 32 px (row = wm>>1, whalf = wm&1)
    const int wn   = wid >> 2;         // 2 N-blocks of 32 filters
    const int h0   = blockIdx.x * 2;   // 31 tiles * 2 = 62 = Ho exactly
    const int fh   = blockIdx.y;       // filter half: 64 filters
    const int bz   = blockIdx.z;

    const uint32_t sb = smem_u32(smem_raw);

    // ---- resident weight load: this CTA's 64 filters, all 9 taps (72KB) ----
    {
        const unsigned char* src = g_W + fh * 8192;     // f-half within tap 0
        #pragma unroll
        for (int j = 0; j < 18; j++) {
            int k = tid + j * 256;                      // 4608 chunks of 16B
            int tap = k >> 9;                           // 512 chunks per tap (8KB)
            int rem = k & 511;
            uint32_t dst = sb + WOFF + (uint32_t)k * 16;
            asm volatile("cp.async.cg.shared.global [%0], [%1], 16;"
                         :: "r"(dst), "l"(src + (size_t)tap * 16384 + rem * 16));
        }
        asm volatile("cp.async.commit_group;");
    }

    // zero pad rows 256..257 of slab
    if (tid < 16) {
        *(uint4*)(smem_raw + 256 * 128 + tid * 16) = make_uint4(0u, 0u, 0u, 0u);
    }

    // ---- slab: x[bz, :, h0..h0+3, :] -> fp16, row=(hloc*64+w), 64 c, SW128 ----
    const float* xb = x + (size_t)bz * Cn * Hn * Wn;
    #pragma unroll 1
    for (int it = 0; it < 8; it++) {
        int t    = tid + it * 256;     // 2048 tasks
        int gw   = t & 63;
        int cg   = (t >> 6) & 7;
        int hloc = t >> 9;             // 0..3 (h0 <= 60: all in bounds)
        const float* xp = xb + (size_t)(cg * 8) * (Hn * Wn) + (h0 + hloc) * Wn + gw;
        unsigned short hs[8];
        #pragma unroll
        for (int i = 0; i < 8; i++) {
            __half h = __float2half_rn(xp[(size_t)i * (Hn * Wn)]);
            hs[i] = *(unsigned short*)&h;
        }
        unsigned row  = (unsigned)(hloc * 64 + gw);
        unsigned boff = row * 128 + cg * 16;
        unsigned sw   = boff ^ ((boff >> 3) & 0x70);
        *(uint4*)(smem_raw + sw) =
            make_uint4((uint32_t)hs[0] | ((uint32_t)hs[1] << 16),
                       (uint32_t)hs[2] | ((uint32_t)hs[3] << 16),
                       (uint32_t)hs[4] | ((uint32_t)hs[5] << 16),
                       (uint32_t)hs[6] | ((uint32_t)hs[7] << 16));
    }

    asm volatile("cp.async.wait_group 0;");
    __syncthreads();                   // the ONLY barrier before the epilogue

    float acc[2][4][4];
    #pragma unroll
    for (int mi = 0; mi < 2; mi++)
        #pragma unroll
        for (int ni = 0; ni < 4; ni++)
            #pragma unroll
            for (int q = 0; q < 4; q++) acc[mi][ni][q] = 0.0f;

    // lane-constant addressing
    const int      a_lrow  = lane & 15;
    const uint32_t a_hi16  = (uint32_t)(lane >> 4) * 16;
    const int      fb0     = wn * 32 + (lane & 7) + ((lane >> 4) & 1) * 8;
    const uint32_t b_off16 = (uint32_t)((lane >> 3) & 1) * 16;
    const uint32_t swzB    = (uint32_t)(fb0 & 7) << 4;
    const uint32_t wBase   = sb + WOFF + (uint32_t)fb0 * 128;
    const int      mrow0   = (wm & 1) * 32 + a_lrow;    // w-coordinate base

    #pragma unroll 1
    for (int t = 0; t < 9; t++) {
        const int ki = t / 3;
        const int kj = t - 3 * ki;
        const int sbase = ((wm >> 1) + ki) * 64 + mrow0 + kj;
        const uint32_t swzA  = (uint32_t)(sbase & 7) << 4;
        const uint32_t aBase = sb + (uint32_t)sbase * 128;
        const uint32_t bTap  = wBase + (uint32_t)t * 8192;

        #pragma unroll
        for (int kc = 0; kc < 4; kc++) {
            const uint32_t aoff = ((uint32_t)(kc * 32) + a_hi16) ^ swzA;
            const uint32_t boff = ((uint32_t)(kc * 32) + b_off16) ^ swzB;

            uint32_t A[2][4], Bf[2][4];
            LDSM4(A[0], aBase + aoff);
            LDSM4(A[1], aBase + 2048 + aoff);
            LDSM4(Bf[0], bTap + boff);
            LDSM4(Bf[1], bTap + 2048 + boff);

            #pragma unroll
            for (int mi = 0; mi < 2; mi++)
                #pragma unroll
                for (int bi = 0; bi < 2; bi++) {
                    MMA(acc[mi][2 * bi],     A[mi], Bf[bi][0], Bf[bi][1]);
                    MMA(acc[mi][2 * bi + 1], A[mi], Bf[bi][2], Bf[bi][3]);
                }
        }
    }

    // ---- epilogue: acc -> out[bz, f, oh, ow] + bias ----
    const int oh = h0 + (wm >> 1);
    const int wpx = (wm & 1) * 32;
    #pragma unroll
    for (int ni = 0; ni < 4; ni++) {
        const int f = fh * 64 + wn * 32 + ni * 8 + (lane & 3) * 2;
        const float b0 = __ldg(bias + f);
        const float b1 = __ldg(bias + f + 1);
        float* p0 = out + (((size_t)bz * Fn + f) * HOn + oh) * WOn;
        float* p1 = p0 + (size_t)HOn * WOn;
        #pragma unroll
        for (int mi = 0; mi < 2; mi++) {
            const int w0 = wpx + mi * 16 + (lane >> 2);   // always < 62
            const int w1 = w0 + 8;
            p0[w0] = acc[mi][ni][0] + b0;
            p1[w0] = acc[mi][ni][1] + b1;
            if (w1 < WOn) {
                p0[w1] = acc[mi][ni][2] + b0;
                p1[w1] = acc[mi][ni][3] + b1;
            }
        }
    }
}

extern "C" void kernel_launch(void* const* d_in, const int* in_sizes, int n_in,
                              void* d_out, int out_size) {
    const float* x    = (const float*)d_in[0];   // (32,64,64,64)
    const float* k1   = (const float*)d_in[1];   // (3,3,64,128)
    const float* k2   = (const float*)d_in[2];   // (3,3,64,128)
    const float* bias = (const float*)d_in[3];   // (128,)
    float* out = (float*)d_out;                  // (32,128,62,62)
    (void)in_sizes; (void)n_in; (void)out_size;

    cudaFuncSetAttribute(conv_hmma_kernel,
                         cudaFuncAttributeMaxDynamicSharedMemorySize, SMEM_TOTAL);

    prep_w<<<288, 256>>>(k1, k2);
    dim3 grid(31, 2, 32);              // h-tiles x f-halves x batch = 1984 CTAs
    conv_hmma_kernel<<<grid, 256, SMEM_TOTAL>>>(x, bias, out);
}

// round 7
// speedup vs baseline: 6.2290x; 1.0536x over previous
#include <cuda_runtime.h>
#include <cuda_fp16.h>
#include <cstdint>

// MorphLayer == conv2d(x, exp(k1)-exp(k2), VALID 3x3) + bias  (exact reduction)
// B=32 C=64 H=W=64 -> Ho=Wo=62, F=128.
// HMMA implicit-GEMM, single fp16 product, fp32 acc.
// Persistent-ish CTAs: grid = 2 f-halves x 148 = 296 CTAs (one wave, 2/SM).
// Each CTA: weights (64 filters x 9 taps = 72KB) resident, loops over 7
// consecutive h-tile jobs with a 4-row ROLLING slab (ring slot = gh & 3):
// only 2 new input rows per tile after the first.

#define Hn  64
#define Wn  64
#define HOn 62
#define WOn 62
#define Fn  128
#define Cn  64

#define SLAB_ROWS  258                     // 4 ring slots * 64 + 2 pad rows
#define SLAB_BYTES (SLAB_ROWS * 128)       // 33024
#define WOFF       SLAB_BYTES
#define WRES_BYTES (9 * 64 * 128)          // 73728
#define SMEM_TOTAL (WOFF + WRES_BYTES)     // 106752 -> 2 CTAs/SM

#define JOBS_PER_HALF 992                  // 31 h-tiles * 32 batch
#define NCTA_PER_HALF 148
#define JOBS_PER_CTA  7                    // ceil(992/148)

// Single fp16 weights, SW128-swizzled: [tap][f=128][c=64]
__device__ __align__(16) unsigned char g_W[9 * 16384];

__device__ __forceinline__ uint32_t smem_u32(const void* p) {
    uint32_t a;
    asm("{ .reg .u64 t; cvta.to.shared.u64 t, %1; cvt.u32.u64 %0, t; }" : "=r"(a) : "l"(p));
    return a;
}

#define LDSM4(r, addr)                                                          \
    asm volatile("ldmatrix.sync.aligned.m8n8.x4.shared.b16 {%0,%1,%2,%3}, [%4];" \
                 : "=r"((r)[0]), "=r"((r)[1]), "=r"((r)[2]), "=r"((r)[3])        \
                 : "r"(addr))

#define MMA(d, a, b0, b1)                                                       \
    asm volatile("mma.sync.aligned.m16n8k16.row.col.f32.f16.f16.f32 "           \
                 "{%0,%1,%2,%3}, {%4,%5,%6,%7}, {%8,%9}, {%0,%1,%2,%3};"        \
                 : "+f"((d)[0]), "+f"((d)[1]), "+f"((d)[2]), "+f"((d)[3])        \
                 : "r"((a)[0]), "r"((a)[1]), "r"((a)[2]), "r"((a)[3]),           \
                   "r"(b0), "r"(b1))

// ---------------- weight prep: w = exp(k1)-exp(k2) -> fp16, swizzled ----------------
__global__ void prep_w(const float* __restrict__ k1, const float* __restrict__ k2) {
    int idx = blockIdx.x * 256 + threadIdx.x;       // 73728 = 9*128*64
    int t   = idx >> 13;
    int rem = idx & 8191;
    int f   = rem >> 6;
    int c   = rem & 63;
    int src = (t * 64 + c) * 128 + f;               // k1 layout (kh,kw,C,F)
    float w = expf(k1[src]) - expf(k2[src]);
    __half h = __float2half_rn(w);
    unsigned off = (unsigned)(f * 128 + c * 2);
    off = off ^ ((off >> 3) & 0x70);                // SW128 swizzle
    *(unsigned short*)(g_W + t * 16384 + off) = *(unsigned short*)&h;
}

// ---------------- main kernel ----------------
extern __shared__ char smem_raw[];

__device__ __forceinline__ void build_rows(const float* __restrict__ xb,
                                           char* smem, int tid,
                                           int gh0, int nrows) {
    // tasks = nrows*64*8 ; per iter 256 threads -> 2*nrows iters
    #pragma unroll 1
    for (int it = 0; it < 2 * nrows; it++) {
        int t    = tid + it * 256;
        int gw   = t & 63;
        int cg   = (t >> 6) & 7;
        int hloc = t >> 9;
        int gh   = gh0 + hloc;
        const float* xp = xb + (size_t)(cg * 8) * (Hn * Wn) + gh * Wn + gw;
        unsigned short hs[8];
        #pragma unroll
        for (int i = 0; i < 8; i++) {
            __half h = __float2half_rn(xp[(size_t)i * (Hn * Wn)]);
            hs[i] = *(unsigned short*)&h;
        }
        unsigned row  = (unsigned)((gh & 3) * 64 + gw);     // ring slot
        unsigned boff = row * 128 + cg * 16;
        unsigned sw   = boff ^ ((boff >> 3) & 0x70);
        *(uint4*)(smem + sw) =
            make_uint4((uint32_t)hs[0] | ((uint32_t)hs[1] << 16),
                       (uint32_t)hs[2] | ((uint32_t)hs[3] << 16),
                       (uint32_t)hs[4] | ((uint32_t)hs[5] << 16),
                       (uint32_t)hs[6] | ((uint32_t)hs[7] << 16));
    }
}

__global__ void __launch_bounds__(256, 2)
conv_hmma_kernel(const float* __restrict__ x,
                 const float* __restrict__ bias,
                 float* __restrict__ out) {
    const int tid  = threadIdx.x;
    const int lane = tid & 31;
    const int wid  = tid >> 5;
    const int wm   = wid & 3;          // M block: row = wm>>1, w-half = wm&1
    const int wn   = wid >> 2;         // N block: 32 filters
    const int fh   = blockIdx.x;       // filter half
    const int cid  = blockIdx.y;       // worker id within half

    const int jstart = cid * JOBS_PER_CTA;
    if (jstart >= JOBS_PER_HALF) return;
    const int jend = (jstart + JOBS_PER_CTA < JOBS_PER_HALF)
                   ? jstart + JOBS_PER_CTA : JOBS_PER_HALF;

    const uint32_t sb = smem_u32(smem_raw);

    // ---- resident weight load: 64 filters x 9 taps (72KB), once per CTA ----
    {
        const unsigned char* src = g_W + fh * 8192;
        #pragma unroll
        for (int j = 0; j < 18; j++) {
            int k = tid + j * 256;                  // 4608 chunks of 16B
            int tap = k >> 9;
            int rem = k & 511;
            uint32_t dst = sb + WOFF + (uint32_t)k * 16;
            asm volatile("cp.async.cg.shared.global [%0], [%1], 16;"
                         :: "r"(dst), "l"(src + (size_t)tap * 16384 + rem * 16));
        }
        asm volatile("cp.async.commit_group;");
    }

    // zero pad rows 256..257 (overflow target; values feed discarded outputs)
    if (tid < 16) {
        *(uint4*)(smem_raw + 256 * 128 + tid * 16) = make_uint4(0u, 0u, 0u, 0u);
    }

    // lane-constant addressing
    const int      a_lrow  = lane & 15;
    const uint32_t a_hi16  = (uint32_t)(lane >> 4) * 16;
    const int      fb0     = wn * 32 + (lane & 7) + ((lane >> 4) & 1) * 8;
    const uint32_t b_off16 = (uint32_t)((lane >> 3) & 1) * 16;
    const uint32_t swzB    = (uint32_t)(fb0 & 7) << 4;
    const uint32_t wBase   = sb + WOFF + (uint32_t)fb0 * 128;
    const int      mrow0   = (wm & 1) * 32 + a_lrow;   // w coordinate base

    // bias (constant across tiles) hoisted
    float bv0[4], bv1[4];
    #pragma unroll
    for (int ni = 0; ni < 4; ni++) {
        const int f = fh * 64 + wn * 32 + ni * 8 + (lane & 3) * 2;
        bv0[ni] = __ldg(bias + f);
        bv1[ni] = __ldg(bias + f + 1);
    }

    // ---- build slab for first job ----
    int j0bz = jstart / 31;
    int j0ht = jstart - j0bz * 31;
    build_rows(x + (size_t)j0bz * Cn * Hn * Wn, smem_raw, tid, 2 * j0ht, 4);
    asm volatile("cp.async.wait_group 0;");

    #pragma unroll 1
    for (int j = jstart; j < jend; j++) {
        const int bz = j / 31;
        const int ht = j - bz * 31;
        const int h0 = 2 * ht;

        __syncthreads();               // slab writes visible to all

        float acc[2][4][4];
        #pragma unroll
        for (int mi = 0; mi < 2; mi++)
            #pragma unroll
            for (int ni = 0; ni < 4; ni++)
                #pragma unroll
                for (int q = 0; q < 4; q++) acc[mi][ni][q] = 0.0f;

        #pragma unroll 1
        for (int t = 0; t < 9; t++) {
            const int ki = t / 3;
            const int kj = t - 3 * ki;
            const int slot = (h0 + (wm >> 1) + ki) & 3;
            const int sbase = slot * 64 + mrow0 + kj;
            const uint32_t swzA  = (uint32_t)(sbase & 7) << 4;
            const uint32_t aBase = sb + (uint32_t)sbase * 128;
            const uint32_t bTap  = wBase + (uint32_t)t * 8192;

            #pragma unroll
            for (int kc = 0; kc < 4; kc++) {
                const uint32_t aoff = ((uint32_t)(kc * 32) + a_hi16) ^ swzA;
                const uint32_t boff = ((uint32_t)(kc * 32) + b_off16) ^ swzB;

                uint32_t A[2][4], Bf[2][4];
                LDSM4(A[0], aBase + aoff);
                LDSM4(A[1], aBase + 2048 + aoff);
                LDSM4(Bf[0], bTap + boff);
                LDSM4(Bf[1], bTap + 2048 + boff);

                #pragma unroll
                for (int mi = 0; mi < 2; mi++)
                    #pragma unroll
                    for (int bi = 0; bi < 2; bi++) {
                        MMA(acc[mi][2 * bi],     A[mi], Bf[bi][0], Bf[bi][1]);
                        MMA(acc[mi][2 * bi + 1], A[mi], Bf[bi][2], Bf[bi][3]);
                    }
            }
        }

        __syncthreads();               // all reads done; slab slots reusable

        // ---- build slab for next job (overlaps epilogue issue) ----
        if (j + 1 < jend) {
            const int nbz = (j + 1) / 31;
            const int nht = (j + 1) - nbz * 31;
            const float* nxb = x + (size_t)nbz * Cn * Hn * Wn;
            if (nht != 0) {
                build_rows(nxb, smem_raw, tid, 2 * nht + 2, 2);   // 2 new rows
            } else {
                build_rows(nxb, smem_raw, tid, 0, 4);             // batch switch
            }
        }

        // ---- epilogue: acc -> out[bz, f, oh, ow] + bias ----
        const int oh  = h0 + (wm >> 1);
        const int wpx = (wm & 1) * 32;
        #pragma unroll
        for (int ni = 0; ni < 4; ni++) {
            const int f = fh * 64 + wn * 32 + ni * 8 + (lane & 3) * 2;
            float* p0 = out + (((size_t)bz * Fn + f) * HOn + oh) * WOn;
            float* p1 = p0 + (size_t)HOn * WOn;
            #pragma unroll
            for (int mi = 0; mi < 2; mi++) {
                const int w0 = wpx + mi * 16 + (lane >> 2);   // always < 62
                const int w1 = w0 + 8;
                p0[w0] = acc[mi][ni][0] + bv0[ni];
                p1[w0] = acc[mi][ni][1] + bv1[ni];
                if (w1 < WOn) {
                    p0[w1] = acc[mi][ni][2] + bv0[ni];
                    p1[w1] = acc[mi][ni][3] + bv1[ni];
                }
            }
        }
    }
}

extern "C" void kernel_launch(void* const* d_in, const int* in_sizes, int n_in,
                              void* d_out, int out_size) {
    const float* x    = (const float*)d_in[0];   // (32,64,64,64)
    const float* k1   = (const float*)d_in[1];   // (3,3,64,128)
    const float* k2   = (const float*)d_in[2];   // (3,3,64,128)
    const float* bias = (const float*)d_in[3];   // (128,)
    float* out = (float*)d_out;                  // (32,128,62,62)
    (void)in_sizes; (void)n_in; (void)out_size;

    cudaFuncSetAttribute(conv_hmma_kernel,
                         cudaFuncAttributeMaxDynamicSharedMemorySize, SMEM_TOTAL);

    prep_w<<<288, 256>>>(k1, k2);
    dim3 grid(2, NCTA_PER_HALF);       // 296 CTAs = one full wave at 2/SM
    conv_hmma_kernel<<<grid, 256, SMEM_TOTAL>>>(x, bias, out);
}